// round 6
// baseline (speedup 1.0000x reference)
#include <cuda_runtime.h>

// ---------------------------------------------------------------------------
// Compile-time G(3,0,1) blade algebra (verified: rel_err 8.5e-8).
// Basis order: 0:1 1:e0 2:e1 3:e2 4:e3 5:e01 6:e02 7:e03 8:e12 9:e13 10:e23
//              11:e012 12:e013 13:e023 14:e123 15:e0123
// ---------------------------------------------------------------------------

namespace ga {

__host__ __device__ constexpr int mask_of(int i) {
    const int t[16] = {0, 1, 2, 4, 8, 3, 5, 9, 6, 10, 12, 7, 11, 13, 14, 15};
    return t[i];
}
__host__ __device__ constexpr int idx_of(int m) {
    const int t[16] = {0, 1, 2, 5, 3, 6, 8, 11, 4, 7, 9, 12, 10, 13, 14, 15};
    return t[m];
}
__host__ __device__ constexpr int popc4(int m) {
    return (m & 1) + ((m >> 1) & 1) + ((m >> 2) & 1) + ((m >> 3) & 1);
}
__host__ __device__ constexpr int rsign(int a, int b) {
    int cnt = 0;
    for (int i = 1; i < 4; ++i)
        if ((a >> i) & 1) cnt += popc4(b & ((1 << i) - 1));
    return (cnt & 1) ? -1 : 1;
}

__host__ __device__ constexpr int gp_coef(int k, int j) {
    const int mk = mask_of(k), mj = mask_of(j);
    const int mi = mk ^ mj;
    if (mi & mj & 1) return 0;              // shared e0 -> metric 0
    return rsign(mi, mj);
}
__host__ __device__ constexpr int gp_src(int k, int j) {
    return idx_of(mask_of(k) ^ mask_of(j));
}

__host__ __device__ constexpr int jn_coef(int k, int j) {
    const int mk = mask_of(k), mj = mask_of(j);
    const int nmj = ~mj & 15;
    if (mk & nmj) return 0;                 // requires mk subset of mj
    const int mi = mk | nmj;
    return rsign(~mk & 15, mk)
         * rsign(mi, ~mi & 15)
         * rsign(mj, ~mj & 15)
         * rsign(~mi & 15, nmj);
}
__host__ __device__ constexpr int jn_src(int k, int j) {
    const int mk = mask_of(k), mj = mask_of(j);
    return idx_of(mk | (~mj & 15));
}

// -------- compile-time unrolled accumulators (literal register indices) ----

template <int K, int J>
__device__ __forceinline__ float gp_term(const float (&x)[16], const float (&y)[16]) {
    if constexpr (J >= 16) {
        return 0.0f;
    } else {
        float acc = gp_term<K, J + 1>(x, y);
        constexpr int c = gp_coef(K, J);
        constexpr int p = gp_src(K, J);
        if constexpr (c == 1)  acc = fmaf(x[p], y[J], acc);
        if constexpr (c == -1) acc = fmaf(-x[p], y[J], acc);
        return acc;
    }
}

template <int K, int J>
__device__ __forceinline__ float jn_term(const float (&x)[16], const float (&y)[16]) {
    if constexpr (J >= 16) {
        return 0.0f;
    } else {
        float acc = jn_term<K, J + 1>(x, y);
        constexpr int c = jn_coef(K, J);
        constexpr int p = jn_src(K, J);
        if constexpr (c == 1)  acc = fmaf(x[p], y[J], acc);
        if constexpr (c == -1) acc = fmaf(-x[p], y[J], acc);
        return acc;
    }
}

template <int K>
__device__ __forceinline__ float4 gp_quad(const float (&x)[16], const float (&y)[16]) {
    return make_float4(gp_term<K + 0, 0>(x, y), gp_term<K + 1, 0>(x, y),
                       gp_term<K + 2, 0>(x, y), gp_term<K + 3, 0>(x, y));
}

template <int K>
__device__ __forceinline__ float4 jn_quad(const float (&x)[16], const float (&y)[16],
                                          float r15) {
    return make_float4(r15 * jn_term<K + 0, 0>(x, y), r15 * jn_term<K + 1, 0>(x, y),
                       r15 * jn_term<K + 2, 0>(x, y), r15 * jn_term<K + 3, 0>(x, y));
}

}  // namespace ga

// ---------------------------------------------------------------------------
// R3 config (best known: 1 pt/thread, streaming hints, per-quad stores) with
// the occupancy pushed from 5 -> 6 CTAs/SM via a 42-register budget.
// Join quads computed first so r15 dies early.
// ---------------------------------------------------------------------------

__global__ __launch_bounds__(256, 6)
void MVGeometricBilinear_kernel(const float4* __restrict__ x4,
                                const float4* __restrict__ y4,
                                const float* __restrict__ ref,
                                float4* __restrict__ o4,
                                int npts) {
    const int p = blockIdx.x * blockDim.x + threadIdx.x;
    if (p >= npts) return;

    float x[16], y[16];
#pragma unroll
    for (int q = 0; q < 4; ++q) {
        const float4 vx = __ldcs(x4 + p * 4 + q);
        const float4 vy = __ldcs(y4 + p * 4 + q);
        x[4 * q + 0] = vx.x; x[4 * q + 1] = vx.y;
        x[4 * q + 2] = vx.z; x[4 * q + 3] = vx.w;
        y[4 * q + 0] = vy.x; y[4 * q + 1] = vy.y;
        y[4 * q + 2] = vy.z; y[4 * q + 3] = vy.w;
    }
    const float r15 = __ldcs(ref + p * 16 + 15);

    float4* outp = o4 + p * 8;

    // Join first (r15 dies after this phase)
    __stcs(outp + 4, ga::jn_quad<0>(x, y, r15));
    __stcs(outp + 5, ga::jn_quad<4>(x, y, r15));
    __stcs(outp + 6, ga::jn_quad<8>(x, y, r15));
    __stcs(outp + 7, ga::jn_quad<12>(x, y, r15));

    // Geometric product
    __stcs(outp + 0, ga::gp_quad<0>(x, y));
    __stcs(outp + 1, ga::gp_quad<4>(x, y));
    __stcs(outp + 2, ga::gp_quad<8>(x, y));
    __stcs(outp + 3, ga::gp_quad<12>(x, y));
}

extern "C" void kernel_launch(void* const* d_in, const int* in_sizes, int n_in,
                              void* d_out, int out_size) {
    const float* x   = (const float*)d_in[0];
    const float* y   = (const float*)d_in[1];
    const float* ref = (const float*)d_in[2];
    float* out       = (float*)d_out;

    const int npts = in_sizes[0] / 16;
    const int threads = 256;
    const int blocks = (npts + threads - 1) / threads;

    MVGeometricBilinear_kernel<<<blocks, threads>>>(
        (const float4*)x, (const float4*)y, ref, (float4*)out, npts);
}

// round 7
// speedup vs baseline: 1.2711x; 1.2711x over previous
#include <cuda_runtime.h>

// ---------------------------------------------------------------------------
// Compile-time G(3,0,1) blade algebra (verified: rel_err 8.5e-8).
// Basis order: 0:1 1:e0 2:e1 3:e2 4:e3 5:e01 6:e02 7:e03 8:e12 9:e13 10:e23
//              11:e012 12:e013 13:e023 14:e123 15:e0123
// ---------------------------------------------------------------------------

namespace ga {

__host__ __device__ constexpr int mask_of(int i) {
    const int t[16] = {0, 1, 2, 4, 8, 3, 5, 9, 6, 10, 12, 7, 11, 13, 14, 15};
    return t[i];
}
__host__ __device__ constexpr int idx_of(int m) {
    const int t[16] = {0, 1, 2, 5, 3, 6, 8, 11, 4, 7, 9, 12, 10, 13, 14, 15};
    return t[m];
}
__host__ __device__ constexpr int popc4(int m) {
    return (m & 1) + ((m >> 1) & 1) + ((m >> 2) & 1) + ((m >> 3) & 1);
}
__host__ __device__ constexpr int rsign(int a, int b) {
    int cnt = 0;
    for (int i = 1; i < 4; ++i)
        if ((a >> i) & 1) cnt += popc4(b & ((1 << i) - 1));
    return (cnt & 1) ? -1 : 1;
}

__host__ __device__ constexpr int gp_coef(int k, int j) {
    const int mk = mask_of(k), mj = mask_of(j);
    const int mi = mk ^ mj;
    if (mi & mj & 1) return 0;              // shared e0 -> metric 0
    return rsign(mi, mj);
}
__host__ __device__ constexpr int gp_src(int k, int j) {
    return idx_of(mask_of(k) ^ mask_of(j));
}

__host__ __device__ constexpr int jn_coef(int k, int j) {
    const int mk = mask_of(k), mj = mask_of(j);
    const int nmj = ~mj & 15;
    if (mk & nmj) return 0;                 // requires mk subset of mj
    const int mi = mk | nmj;
    return rsign(~mk & 15, mk)
         * rsign(mi, ~mi & 15)
         * rsign(mj, ~mj & 15)
         * rsign(~mi & 15, nmj);
}
__host__ __device__ constexpr int jn_src(int k, int j) {
    const int mk = mask_of(k), mj = mask_of(j);
    return idx_of(mk | (~mj & 15));
}

// -------- compile-time unrolled accumulators (literal register indices) ----

template <int K, int J>
__device__ __forceinline__ float gp_term(const float (&x)[16], const float (&y)[16]) {
    if constexpr (J >= 16) {
        return 0.0f;
    } else {
        float acc = gp_term<K, J + 1>(x, y);
        constexpr int c = gp_coef(K, J);
        constexpr int p = gp_src(K, J);
        if constexpr (c == 1)  acc = fmaf(x[p], y[J], acc);
        if constexpr (c == -1) acc = fmaf(-x[p], y[J], acc);
        return acc;
    }
}

template <int K, int J>
__device__ __forceinline__ float jn_term(const float (&x)[16], const float (&y)[16]) {
    if constexpr (J >= 16) {
        return 0.0f;
    } else {
        float acc = jn_term<K, J + 1>(x, y);
        constexpr int c = jn_coef(K, J);
        constexpr int p = jn_src(K, J);
        if constexpr (c == 1)  acc = fmaf(x[p], y[J], acc);
        if constexpr (c == -1) acc = fmaf(-x[p], y[J], acc);
        return acc;
    }
}

template <int K>
__device__ __forceinline__ float4 gp_quad(const float (&x)[16], const float (&y)[16]) {
    return make_float4(gp_term<K + 0, 0>(x, y), gp_term<K + 1, 0>(x, y),
                       gp_term<K + 2, 0>(x, y), gp_term<K + 3, 0>(x, y));
}

template <int K>
__device__ __forceinline__ float4 jn_quad(const float (&x)[16], const float (&y)[16],
                                          float r15) {
    return make_float4(r15 * jn_term<K + 0, 0>(x, y), r15 * jn_term<K + 1, 0>(x, y),
                       r15 * jn_term<K + 2, 0>(x, y), r15 * jn_term<K + 3, 0>(x, y));
}

}  // namespace ga

// ---------------------------------------------------------------------------
// R3 body (48 regs, 5 CTAs/SM — the proven sweet spot) wrapped in a
// persistent grid-stride loop with ZERO-register-cost L2 prefetch of the
// next iteration's lines. Prefetch is fire-and-forget: DRAM is fed
// continuously while demand loads hit L2 (~250cyc instead of ~600).
// ---------------------------------------------------------------------------

__device__ __forceinline__ void l2_prefetch(const void* p) {
    asm volatile("prefetch.global.L2 [%0];" :: "l"(p));
}

__global__ __launch_bounds__(256, 5)
void MVGeometricBilinear_kernel(const float4* __restrict__ x4,
                                const float4* __restrict__ y4,
                                const float* __restrict__ ref,
                                float4* __restrict__ o4,
                                int npts) {
    const int stride = gridDim.x * blockDim.x;

#pragma unroll 1
    for (int p = blockIdx.x * blockDim.x + threadIdx.x; p < npts; p += stride) {
        // ---- prefetch next iteration's data into L2 (no registers held) ----
        const int pn = p + stride;
        if (pn < npts) {
            l2_prefetch(x4 + pn * 4);        // 64B (shares 128B line w/ neighbor)
            l2_prefetch(y4 + pn * 4);
            l2_prefetch(ref + pn * 16 + 15);
        }

        // ---- demand loads (R3 pattern) ----
        float x[16], y[16];
#pragma unroll
        for (int q = 0; q < 4; ++q) {
            const float4 vx = __ldcs(x4 + p * 4 + q);
            const float4 vy = __ldcs(y4 + p * 4 + q);
            x[4 * q + 0] = vx.x; x[4 * q + 1] = vx.y;
            x[4 * q + 2] = vx.z; x[4 * q + 3] = vx.w;
            y[4 * q + 0] = vy.x; y[4 * q + 1] = vy.y;
            y[4 * q + 2] = vy.z; y[4 * q + 3] = vy.w;
        }
        const float r15 = __ldcs(ref + p * 16 + 15);

        float4* outp = o4 + p * 8;

        // GP quads (R3 order), stored immediately to keep live set minimal
        __stcs(outp + 0, ga::gp_quad<0>(x, y));
        __stcs(outp + 1, ga::gp_quad<4>(x, y));
        __stcs(outp + 2, ga::gp_quad<8>(x, y));
        __stcs(outp + 3, ga::gp_quad<12>(x, y));

        // Join quads
        __stcs(outp + 4, ga::jn_quad<0>(x, y, r15));
        __stcs(outp + 5, ga::jn_quad<4>(x, y, r15));
        __stcs(outp + 6, ga::jn_quad<8>(x, y, r15));
        __stcs(outp + 7, ga::jn_quad<12>(x, y, r15));
    }
}

extern "C" void kernel_launch(void* const* d_in, const int* in_sizes, int n_in,
                              void* d_out, int out_size) {
    const float* x   = (const float*)d_in[0];
    const float* y   = (const float*)d_in[1];
    const float* ref = (const float*)d_in[2];
    float* out       = (float*)d_out;

    const int npts = in_sizes[0] / 16;
    const int threads = 256;
    // persistent: exactly one full residency (5 CTAs/SM x 148 SMs)
    int blocks = 148 * 5;
    const int max_blocks = (npts + threads - 1) / threads;
    if (blocks > max_blocks) blocks = max_blocks;

    MVGeometricBilinear_kernel<<<blocks, threads>>>(
        (const float4*)x, (const float4*)y, ref, (float4*)out, npts);
}

// round 8
// speedup vs baseline: 1.7599x; 1.3845x over previous
#include <cuda_runtime.h>

// ---------------------------------------------------------------------------
// Compile-time G(3,0,1) blade algebra (verified: rel_err 8.5e-8).
// Basis order: 0:1 1:e0 2:e1 3:e2 4:e3 5:e01 6:e02 7:e03 8:e12 9:e13 10:e23
//              11:e012 12:e013 13:e023 14:e123 15:e0123
// ---------------------------------------------------------------------------

namespace ga {

__host__ __device__ constexpr int mask_of(int i) {
    const int t[16] = {0, 1, 2, 4, 8, 3, 5, 9, 6, 10, 12, 7, 11, 13, 14, 15};
    return t[i];
}
__host__ __device__ constexpr int idx_of(int m) {
    const int t[16] = {0, 1, 2, 5, 3, 6, 8, 11, 4, 7, 9, 12, 10, 13, 14, 15};
    return t[m];
}
__host__ __device__ constexpr int popc4(int m) {
    return (m & 1) + ((m >> 1) & 1) + ((m >> 2) & 1) + ((m >> 3) & 1);
}
__host__ __device__ constexpr int rsign(int a, int b) {
    int cnt = 0;
    for (int i = 1; i < 4; ++i)
        if ((a >> i) & 1) cnt += popc4(b & ((1 << i) - 1));
    return (cnt & 1) ? -1 : 1;
}

__host__ __device__ constexpr int gp_coef(int k, int j) {
    const int mk = mask_of(k), mj = mask_of(j);
    const int mi = mk ^ mj;
    if (mi & mj & 1) return 0;              // shared e0 -> metric 0
    return rsign(mi, mj);
}
__host__ __device__ constexpr int gp_src(int k, int j) {
    return idx_of(mask_of(k) ^ mask_of(j));
}

__host__ __device__ constexpr int jn_coef(int k, int j) {
    const int mk = mask_of(k), mj = mask_of(j);
    const int nmj = ~mj & 15;
    if (mk & nmj) return 0;                 // requires mk subset of mj
    const int mi = mk | nmj;
    return rsign(~mk & 15, mk)
         * rsign(mi, ~mi & 15)
         * rsign(mj, ~mj & 15)
         * rsign(~mi & 15, nmj);
}
__host__ __device__ constexpr int jn_src(int k, int j) {
    const int mk = mask_of(k), mj = mask_of(j);
    return idx_of(mk | (~mj & 15));
}

// -------- compile-time unrolled accumulators (literal register indices) ----

template <int K, int J>
__device__ __forceinline__ float gp_term(const float (&x)[16], const float (&y)[16]) {
    if constexpr (J >= 16) {
        return 0.0f;
    } else {
        float acc = gp_term<K, J + 1>(x, y);
        constexpr int c = gp_coef(K, J);
        constexpr int p = gp_src(K, J);
        if constexpr (c == 1)  acc = fmaf(x[p], y[J], acc);
        if constexpr (c == -1) acc = fmaf(-x[p], y[J], acc);
        return acc;
    }
}

template <int K, int J>
__device__ __forceinline__ float jn_term(const float (&x)[16], const float (&y)[16]) {
    if constexpr (J >= 16) {
        return 0.0f;
    } else {
        float acc = jn_term<K, J + 1>(x, y);
        constexpr int c = jn_coef(K, J);
        constexpr int p = jn_src(K, J);
        if constexpr (c == 1)  acc = fmaf(x[p], y[J], acc);
        if constexpr (c == -1) acc = fmaf(-x[p], y[J], acc);
        return acc;
    }
}

}  // namespace ga

// ---------------------------------------------------------------------------
// R3 skeleton + warp-private smem transpose of the OUTPUT stream.
//
// Why: ncu shows L1tex (wavefront queue) is the binding pipe (66.7%).
// Per-thread strided STG.128 costs 32 wavefronts/instr (one 128B line per
// lane). Since one point's output (32 floats) == warp width, routing through
// smem rows of pitch 33 gives conflict-free STS/LDS and 32 fully-coalesced
// STG.32 (1 wavefront each): store wavefronts drop 256 -> 32 per warp.
// ---------------------------------------------------------------------------

constexpr int TPB = 256;
constexpr int WARPS_PER_CTA = TPB / 32;
constexpr int PITCH = 33;                       // floats; bank = (row + col) % 32

__global__ __launch_bounds__(TPB, 5)
void MVGeometricBilinear_kernel(const float4* __restrict__ x4,
                                const float4* __restrict__ y4,
                                const float* __restrict__ ref,
                                float* __restrict__ out,
                                int npts) {
    __shared__ float tr[WARPS_PER_CTA][32 * PITCH];   // 33792 B

    const int tid  = threadIdx.x;
    const int lane = tid & 31;
    const int w    = tid >> 5;
    const int p    = blockIdx.x * TPB + tid;          // this thread's point
    const int P0   = p - lane;                        // warp's first point

    float* row = &tr[w][lane * PITCH];

    if (p < npts) {
        float x[16], y[16];
#pragma unroll
        for (int q = 0; q < 4; ++q) {
            const float4 vx = __ldcs(x4 + p * 4 + q);
            const float4 vy = __ldcs(y4 + p * 4 + q);
            x[4 * q + 0] = vx.x; x[4 * q + 1] = vx.y;
            x[4 * q + 2] = vx.z; x[4 * q + 3] = vx.w;
            y[4 * q + 0] = vy.x; y[4 * q + 1] = vy.y;
            y[4 * q + 2] = vy.z; y[4 * q + 3] = vy.w;
        }
        const float r15 = __ldcs(ref + p * 16 + 15);

        // GP outputs k=0..15 -> smem row, one output at a time (small live set)
#pragma unroll
        for (int k = 0; k < 16; ++k) {
            float v;
            switch (k) {   // force separate constexpr instantiations
                case 0:  v = ga::gp_term<0, 0>(x, y);  break;
                case 1:  v = ga::gp_term<1, 0>(x, y);  break;
                case 2:  v = ga::gp_term<2, 0>(x, y);  break;
                case 3:  v = ga::gp_term<3, 0>(x, y);  break;
                case 4:  v = ga::gp_term<4, 0>(x, y);  break;
                case 5:  v = ga::gp_term<5, 0>(x, y);  break;
                case 6:  v = ga::gp_term<6, 0>(x, y);  break;
                case 7:  v = ga::gp_term<7, 0>(x, y);  break;
                case 8:  v = ga::gp_term<8, 0>(x, y);  break;
                case 9:  v = ga::gp_term<9, 0>(x, y);  break;
                case 10: v = ga::gp_term<10, 0>(x, y); break;
                case 11: v = ga::gp_term<11, 0>(x, y); break;
                case 12: v = ga::gp_term<12, 0>(x, y); break;
                case 13: v = ga::gp_term<13, 0>(x, y); break;
                case 14: v = ga::gp_term<14, 0>(x, y); break;
                default: v = ga::gp_term<15, 0>(x, y); break;
            }
            row[k] = v;
        }
        // Join outputs k=0..15 (scaled by r15)
#pragma unroll
        for (int k = 0; k < 16; ++k) {
            float v;
            switch (k) {
                case 0:  v = ga::jn_term<0, 0>(x, y);  break;
                case 1:  v = ga::jn_term<1, 0>(x, y);  break;
                case 2:  v = ga::jn_term<2, 0>(x, y);  break;
                case 3:  v = ga::jn_term<3, 0>(x, y);  break;
                case 4:  v = ga::jn_term<4, 0>(x, y);  break;
                case 5:  v = ga::jn_term<5, 0>(x, y);  break;
                case 6:  v = ga::jn_term<6, 0>(x, y);  break;
                case 7:  v = ga::jn_term<7, 0>(x, y);  break;
                case 8:  v = ga::jn_term<8, 0>(x, y);  break;
                case 9:  v = ga::jn_term<9, 0>(x, y);  break;
                case 10: v = ga::jn_term<10, 0>(x, y); break;
                case 11: v = ga::jn_term<11, 0>(x, y); break;
                case 12: v = ga::jn_term<12, 0>(x, y); break;
                case 13: v = ga::jn_term<13, 0>(x, y); break;
                default: v = ga::jn_term<15, 0>(x, y); break;
                case 14: v = ga::jn_term<14, 0>(x, y); break;
            }
            row[16 + k] = r15 * v;
        }
    }
    __syncwarp();

    // Coalesced writeback: instruction i covers point P0+i (128B line).
    // Element (32i + lane) of the warp's output region = (row i, comp lane).
    const int nvalid = npts - P0;                     // points valid in warp
    float* outw = out + (size_t)P0 * 32;
    if (nvalid >= 32) {
#pragma unroll
        for (int i = 0; i < 32; ++i)
            __stcs(outw + 32 * i + lane, tr[w][i * PITCH + lane]);
    } else {
        for (int i = 0; i < nvalid; ++i)
            __stcs(outw + 32 * i + lane, tr[w][i * PITCH + lane]);
    }
}

extern "C" void kernel_launch(void* const* d_in, const int* in_sizes, int n_in,
                              void* d_out, int out_size) {
    const float* x   = (const float*)d_in[0];
    const float* y   = (const float*)d_in[1];
    const float* ref = (const float*)d_in[2];
    float* out       = (float*)d_out;

    const int npts = in_sizes[0] / 16;
    const int blocks = (npts + TPB - 1) / TPB;

    MVGeometricBilinear_kernel<<<blocks, TPB>>>(
        (const float4*)x, (const float4*)y, ref, out, npts);
}

// round 9
// speedup vs baseline: 1.8134x; 1.0304x over previous
#include <cuda_runtime.h>

// ---------------------------------------------------------------------------
// Compile-time G(3,0,1) blade algebra (verified: rel_err 8.5e-8).
// Basis order: 0:1 1:e0 2:e1 3:e2 4:e3 5:e01 6:e02 7:e03 8:e12 9:e13 10:e23
//              11:e012 12:e013 13:e023 14:e123 15:e0123
// ---------------------------------------------------------------------------

namespace ga {

__host__ __device__ constexpr int mask_of(int i) {
    const int t[16] = {0, 1, 2, 4, 8, 3, 5, 9, 6, 10, 12, 7, 11, 13, 14, 15};
    return t[i];
}
__host__ __device__ constexpr int idx_of(int m) {
    const int t[16] = {0, 1, 2, 5, 3, 6, 8, 11, 4, 7, 9, 12, 10, 13, 14, 15};
    return t[m];
}
__host__ __device__ constexpr int popc4(int m) {
    return (m & 1) + ((m >> 1) & 1) + ((m >> 2) & 1) + ((m >> 3) & 1);
}
__host__ __device__ constexpr int rsign(int a, int b) {
    int cnt = 0;
    for (int i = 1; i < 4; ++i)
        if ((a >> i) & 1) cnt += popc4(b & ((1 << i) - 1));
    return (cnt & 1) ? -1 : 1;
}

__host__ __device__ constexpr int gp_coef(int k, int j) {
    const int mk = mask_of(k), mj = mask_of(j);
    const int mi = mk ^ mj;
    if (mi & mj & 1) return 0;              // shared e0 -> metric 0
    return rsign(mi, mj);
}
__host__ __device__ constexpr int gp_src(int k, int j) {
    return idx_of(mask_of(k) ^ mask_of(j));
}

__host__ __device__ constexpr int jn_coef(int k, int j) {
    const int mk = mask_of(k), mj = mask_of(j);
    const int nmj = ~mj & 15;
    if (mk & nmj) return 0;                 // requires mk subset of mj
    const int mi = mk | nmj;
    return rsign(~mk & 15, mk)
         * rsign(mi, ~mi & 15)
         * rsign(mj, ~mj & 15)
         * rsign(~mi & 15, nmj);
}
__host__ __device__ constexpr int jn_src(int k, int j) {
    const int mk = mask_of(k), mj = mask_of(j);
    return idx_of(mk | (~mj & 15));
}

template <int K, int J>
__device__ __forceinline__ float gp_term(const float (&x)[16], const float (&y)[16]) {
    if constexpr (J >= 16) {
        return 0.0f;
    } else {
        float acc = gp_term<K, J + 1>(x, y);
        constexpr int c = gp_coef(K, J);
        constexpr int p = gp_src(K, J);
        if constexpr (c == 1)  acc = fmaf(x[p], y[J], acc);
        if constexpr (c == -1) acc = fmaf(-x[p], y[J], acc);
        return acc;
    }
}

template <int K, int J>
__device__ __forceinline__ float jn_term(const float (&x)[16], const float (&y)[16]) {
    if constexpr (J >= 16) {
        return 0.0f;
    } else {
        float acc = jn_term<K, J + 1>(x, y);
        constexpr int c = jn_coef(K, J);
        constexpr int p = jn_src(K, J);
        if constexpr (c == 1)  acc = fmaf(x[p], y[J], acc);
        if constexpr (c == -1) acc = fmaf(-x[p], y[J], acc);
        return acc;
    }
}

}  // namespace ga

// ---------------------------------------------------------------------------
// Full transpose pipeline (both directions through warp-private smem):
//   1. warp loads its 32-point x/y block with COALESCED LDG.128
//      (4 wf/instr instead of 16) into smem, chunk-major stride 136 floats
//      (bank(start) = 8c + 4p mod 32: conflict-free for STS.128 and LDS.128)
//   2. each thread LDS.128s its own point into registers, computes
//   3. outputs transposed back out through the SAME buffer (pitch 33) and
//      written with 32 coalesced STG.32 (R8 scheme, proven -6us)
// gmem wavefronts per warp: 240 -> ~80. L1tex stops binding; DRAM takes over.
// ---------------------------------------------------------------------------

constexpr int TPB = 256;
constexpr int WARPS_PER_CTA = TPB / 32;
constexpr int CH_STRIDE = 136;   // floats between chunk planes (544B)
constexpr int WBUF = 8 * CH_STRIDE;  // 1088 floats = 4352B (>= 32*33 for output)
constexpr int PITCH = 33;        // output transpose pitch (floats)

__global__ __launch_bounds__(TPB, 5)
void MVGeometricBilinear_kernel(const float4* __restrict__ x4,
                                const float4* __restrict__ y4,
                                const float* __restrict__ ref,
                                float* __restrict__ out,
                                int npts) {
    __shared__ float smem[WARPS_PER_CTA][WBUF];      // 34816 B

    const int tid  = threadIdx.x;
    const int lane = tid & 31;
    const int w    = tid >> 5;
    const int P0   = blockIdx.x * TPB + w * 32;      // warp's first point
    const int p    = P0 + lane;

    float* wbuf = smem[w];

    // ---- 1. coalesced gmem -> smem (x and y, 4 LDG.128 each) ----
    {
        const int nv  = npts - P0;
        const int nv4 = nv <= 0 ? 0 : (nv >= 32 ? 128 : nv * 4);
        const float4* xw = x4 + (size_t)P0 * 4;
        const float4* yw = y4 + (size_t)P0 * 4;
#pragma unroll
        for (int i = 0; i < 4; ++i) {
            const int g = i * 32 + lane;             // float4 index in block
            if (g < nv4) {
                const int c  = g & 3;                // chunk within point
                const int pp = g >> 2;               // local point
                *(float4*)(wbuf + c * CH_STRIDE + pp * 4)       = __ldcs(xw + g);
                *(float4*)(wbuf + (4 + c) * CH_STRIDE + pp * 4) = __ldcs(yw + g);
            }
        }
    }
    const float r15 = (p < npts) ? __ldcs(ref + (size_t)p * 16 + 15) : 0.0f;
    __syncwarp();

    // ---- 2. smem -> regs (own point), conflict-free LDS.128 ----
    float x[16], y[16];
    if (p < npts) {
#pragma unroll
        for (int c = 0; c < 4; ++c) {
            const float4 vx = *(const float4*)(wbuf + c * CH_STRIDE + lane * 4);
            const float4 vy = *(const float4*)(wbuf + (4 + c) * CH_STRIDE + lane * 4);
            x[4*c+0]=vx.x; x[4*c+1]=vx.y; x[4*c+2]=vx.z; x[4*c+3]=vx.w;
            y[4*c+0]=vy.x; y[4*c+1]=vy.y; y[4*c+2]=vy.z; y[4*c+3]=vy.w;
        }
    }
    __syncwarp();   // all lanes done reading before buffer is overwritten

    // ---- 3. compute -> smem rows (pitch 33, bank = lane+k: conflict-free) ----
    if (p < npts) {
        float* row = wbuf + lane * PITCH;
#pragma unroll
        for (int k = 0; k < 16; ++k) {
            float v;
            switch (k) {
                case 0:  v = ga::gp_term<0, 0>(x, y);  break;
                case 1:  v = ga::gp_term<1, 0>(x, y);  break;
                case 2:  v = ga::gp_term<2, 0>(x, y);  break;
                case 3:  v = ga::gp_term<3, 0>(x, y);  break;
                case 4:  v = ga::gp_term<4, 0>(x, y);  break;
                case 5:  v = ga::gp_term<5, 0>(x, y);  break;
                case 6:  v = ga::gp_term<6, 0>(x, y);  break;
                case 7:  v = ga::gp_term<7, 0>(x, y);  break;
                case 8:  v = ga::gp_term<8, 0>(x, y);  break;
                case 9:  v = ga::gp_term<9, 0>(x, y);  break;
                case 10: v = ga::gp_term<10, 0>(x, y); break;
                case 11: v = ga::gp_term<11, 0>(x, y); break;
                case 12: v = ga::gp_term<12, 0>(x, y); break;
                case 13: v = ga::gp_term<13, 0>(x, y); break;
                case 14: v = ga::gp_term<14, 0>(x, y); break;
                default: v = ga::gp_term<15, 0>(x, y); break;
            }
            row[k] = v;
        }
#pragma unroll
        for (int k = 0; k < 16; ++k) {
            float v;
            switch (k) {
                case 0:  v = ga::jn_term<0, 0>(x, y);  break;
                case 1:  v = ga::jn_term<1, 0>(x, y);  break;
                case 2:  v = ga::jn_term<2, 0>(x, y);  break;
                case 3:  v = ga::jn_term<3, 0>(x, y);  break;
                case 4:  v = ga::jn_term<4, 0>(x, y);  break;
                case 5:  v = ga::jn_term<5, 0>(x, y);  break;
                case 6:  v = ga::jn_term<6, 0>(x, y);  break;
                case 7:  v = ga::jn_term<7, 0>(x, y);  break;
                case 8:  v = ga::jn_term<8, 0>(x, y);  break;
                case 9:  v = ga::jn_term<9, 0>(x, y);  break;
                case 10: v = ga::jn_term<10, 0>(x, y); break;
                case 11: v = ga::jn_term<11, 0>(x, y); break;
                case 12: v = ga::jn_term<12, 0>(x, y); break;
                case 13: v = ga::jn_term<13, 0>(x, y); break;
                case 14: v = ga::jn_term<14, 0>(x, y); break;
                default: v = ga::jn_term<15, 0>(x, y); break;
            }
            row[16 + k] = r15 * v;
        }
    }
    __syncwarp();

    // ---- 4. coalesced writeback: instruction i = point P0+i (one 128B line) ----
    const int nvalid = npts - P0;
    float* outw = out + (size_t)P0 * 32;
    if (nvalid >= 32) {
#pragma unroll
        for (int i = 0; i < 32; ++i)
            __stcs(outw + 32 * i + lane, wbuf[i * PITCH + lane]);
    } else if (nvalid > 0) {
        for (int i = 0; i < nvalid; ++i)
            __stcs(outw + 32 * i + lane, wbuf[i * PITCH + lane]);
    }
}

extern "C" void kernel_launch(void* const* d_in, const int* in_sizes, int n_in,
                              void* d_out, int out_size) {
    const float* x   = (const float*)d_in[0];
    const float* y   = (const float*)d_in[1];
    const float* ref = (const float*)d_in[2];
    float* out       = (float*)d_out;

    const int npts = in_sizes[0] / 16;
    const int blocks = (npts + TPB - 1) / TPB;

    MVGeometricBilinear_kernel<<<blocks, TPB>>>(
        (const float4*)x, (const float4*)y, ref, out, npts);
}